// round 12
// baseline (speedup 1.0000x reference)
#include <cuda_runtime.h>
#include <cuda_fp16.h>
#include <cstdint>
#include <math.h>

// POLY2: out_b = sigmoid( sum_{i<j} w_ij * x_bi * x_bj )
// Legacy-tensor-roof GEMM (512 MAC/cyc/SM) with zero-copy A: X is cp.async'd
// as fp32 and converted to fp16 at fragment-load time (kills the 17us prep
// conversion kernel). fp16 mma m16n8k16 fp16-acc, diag sub-block skip,
// triangular K-skip, 2-stage cp.async, 2 CTAs/SM, heavy-tile-first.

#define F        1024
#define BATCHN   16384
#define M_TILE   128
#define N_TILE   128
#define K_CHUNK  64
#define NTHREADS 256
#define NBLK     8

#define AW          68                      // A smem row stride in words (272B)
#define A_TILE      (128 * AW * 4)          // 34816
#define B_ROW       144
#define B_TILE      (128 * B_ROW)           // 18432
#define STAGE_BYTES (A_TILE + B_TILE)       // 53248
#define PART_OFF    (2 * STAGE_BYTES)       // 106496
#define SMEM_TOTAL  (PART_OFF + 512)        // 107008

__device__ __half d_Wth[F * F];           // Wt[n][k] = w_{k,n} (k<n else 0)
__device__ float  d_part[NBLK * BATCHN];

// ---------------- helpers ----------------
__device__ __forceinline__ uint32_t smem_u32(const void* p) {
    uint32_t a;
    asm("{ .reg .u64 t; cvta.to.shared.u64 t, %1; cvt.u32.u64 %0, t; }" : "=r"(a) : "l"(p));
    return a;
}
__device__ __forceinline__ void cp16(uint32_t dst, const void* src) {
    asm volatile("cp.async.cg.shared.global [%0], [%1], 16;" :: "r"(dst), "l"(src) : "memory");
}
__device__ __forceinline__ void cp_commit() { asm volatile("cp.async.commit_group;" ::: "memory"); }
__device__ __forceinline__ void cp_wait1()  { asm volatile("cp.async.wait_group 1;"  ::: "memory"); }

__device__ __forceinline__ void ldsm4(uint32_t* r, uint32_t addr) {
    asm volatile("ldmatrix.sync.aligned.m8n8.x4.shared.b16 {%0,%1,%2,%3}, [%4];"
        : "=r"(r[0]), "=r"(r[1]), "=r"(r[2]), "=r"(r[3]) : "r"(addr));
}
__device__ __forceinline__ void mma_h(uint32_t* c, const uint32_t* a, uint32_t b0, uint32_t b1) {
    asm volatile(
        "mma.sync.aligned.m16n8k16.row.col.f16.f16.f16.f16 "
        "{%0,%1}, {%2,%3,%4,%5}, {%6,%7}, {%0,%1};"
        : "+r"(c[0]), "+r"(c[1])
        : "r"(a[0]), "r"(a[1]), "r"(a[2]), "r"(a[3]), "r"(b0), "r"(b1));
}
__device__ __forceinline__ uint32_t packh2(float2 v) {
    __half2 h = __floats2half2_rn(v.x, v.y);
    return *reinterpret_cast<uint32_t*>(&h);
}

// ---------------- prep: W scatter only ----------------
__device__ __forceinline__ float w_at(const float* __restrict__ w, int k, int n) {
    if (k >= n) return 0.0f;
    int pi = k * (F - 1) - (k * (k - 1)) / 2 + (n - k - 1);
    return w[pi];
}
__global__ void prep_w_kernel(const float* __restrict__ w) {
    int idx = blockIdx.x * 256 + threadIdx.x;    // F*F/2 half2 slots
    int n  = idx >> 9;
    int k2 = idx & 511;
    float f0 = w_at(w, 2 * k2,     n);
    float f1 = w_at(w, 2 * k2 + 1, n);
    reinterpret_cast<__half2*>(d_Wth)[idx] = __floats2half2_rn(f0, f1);
}

__global__ void sigmoid_kernel(float* __restrict__ out) {
    int i = blockIdx.x * 256 + threadIdx.x;
    float z = 0.0f;
    #pragma unroll
    for (int j = 0; j < NBLK; ++j) z += d_part[j * BATCHN + i];
    out[i] = 1.0f / (1.0f + __expf(-z));
}

// ---------------- chunk compute body ----------------
// A from fp32 smem (LDS.64 + cvt), B via ldmatrix. fp16 chunk-chains flushed
// into packed half2 running accumulators. TAIL: diagonal sub-block skip.
template<bool TAIL>
__device__ __forceinline__ void chunk_body(const float2* __restrict__ As2,
                                           uint32_t bAddr,
                                           uint32_t accH[2][8][2],
                                           int d, int warpN, int warpM, int lane) {
    int r0 = warpM * 32 + (lane >> 2);
    int kw = (lane & 3);                         // fragment k pair idx
    uint32_t a[2][4][4];
    #pragma unroll
    for (int ks = 0; ks < 4; ++ks) {
        int kk2 = ks * 8 + kw;                   // float2 index within 32-pair row
        #pragma unroll
        for (int mt = 0; mt < 2; ++mt) {
            int r = r0 + mt * 16;
            a[mt][ks][0] = packh2(As2[r * (AW / 2) + kk2]);
            a[mt][ks][1] = packh2(As2[(r + 8) * (AW / 2) + kk2]);
            a[mt][ks][2] = packh2(As2[r * (AW / 2) + kk2 + 4]);
            a[mt][ks][3] = packh2(As2[(r + 8) * (AW / 2) + kk2 + 4]);
        }
    }
    #pragma unroll
    for (int g = 0; g < 4; ++g) {
        uint32_t c[4][2] = {{0u,0u},{0u,0u},{0u,0u},{0u,0u}};
        #pragma unroll
        for (int ks = 0; ks < 4; ++ks) {
            if (TAIL) {
                if (!((d + 16 * ks) < (warpN * 64 + (2 * g + 1) * 8 + 8))) continue;
            }
            uint32_t b[4];
            ldsm4(b, bAddr + (uint32_t)(g * 16) * B_ROW + ks * 32);
            bool nz0 = !TAIL || ((d + 16 * ks) < (warpN * 64 + 2 * g * 8 + 8));
            if (nz0) {
                mma_h(c[0], a[0][ks], b[0], b[2]);
                mma_h(c[2], a[1][ks], b[0], b[2]);
            }
            mma_h(c[1], a[0][ks], b[1], b[3]);
            mma_h(c[3], a[1][ks], b[1], b[3]);
        }
        #pragma unroll
        for (int q = 0; q < 2; ++q) {
            #pragma unroll
            for (int r = 0; r < 2; ++r) {
                __half2 v0 = *reinterpret_cast<__half2*>(&c[2 * q][r]);
                __half2 v1 = *reinterpret_cast<__half2*>(&c[2 * q + 1][r]);
                __half2* A0 = reinterpret_cast<__half2*>(&accH[q][2 * g][r]);
                __half2* A1 = reinterpret_cast<__half2*>(&accH[q][2 * g + 1][r]);
                *A0 = __hadd2(*A0, v0);
                *A1 = __hadd2(*A1, v1);
            }
        }
    }
}

// ---------------- main GEMM + fused rowdot ----------------
extern __shared__ char smem_buf[];

__global__ void __launch_bounds__(NTHREADS, 2)
poly2_gemm_kernel(const float* __restrict__ x) {
    uint32_t sb = smem_u32(smem_buf);
    float* part = reinterpret_cast<float*>(smem_buf + PART_OFF);

    int tid  = threadIdx.x;
    int lane = tid & 31;
    int wid  = tid >> 5;
    int warpM = wid & 3;
    int warpN = wid >> 2;
    int m0 = blockIdx.x * M_TILE;
    int by = (int)gridDim.y - 1 - (int)blockIdx.y;   // heavy tiles first
    int n0 = by * N_TILE;

    int nchunks = (n0 + N_TILE) / K_CHUNK;           // 2..16

    // loader bases: A fp32 from x, B fp16 from d_Wth
    const float* agp  = x + (size_t)(m0 + (tid >> 4)) * F + (tid & 15) * 4;
    const __half* bgp = d_Wth + (size_t)(n0 + (tid >> 3)) * F + (tid & 7) * 8;
    uint32_t asd = (uint32_t)((tid >> 4) * (AW * 4) + (tid & 15) * 16);
    uint32_t bsd = (uint32_t)((tid >> 3) * B_ROW + (tid & 7) * 16) + A_TILE;

    #define ISSUE_STAGE(sidx)                                            \
        do {                                                             \
            uint32_t ab = sb + (uint32_t)(sidx) * STAGE_BYTES + asd;     \
            _Pragma("unroll")                                            \
            for (int j = 0; j < 8; ++j)      /* A: 128 rows, fp32 */     \
                cp16(ab + j * (16 * AW * 4), agp + j * (16 * F));        \
            uint32_t bb = sb + (uint32_t)(sidx) * STAGE_BYTES + bsd;     \
            _Pragma("unroll")                                            \
            for (int j = 0; j < 4; ++j)      /* B: 128 rows, fp16 */     \
                cp16(bb + j * (32 * B_ROW), bgp + j * (32 * F));         \
            agp += K_CHUNK; bgp += K_CHUNK;                              \
        } while (0)

    uint32_t accH[2][8][2];
    #pragma unroll
    for (int mt = 0; mt < 2; ++mt)
        #pragma unroll
        for (int nt = 0; nt < 8; ++nt)
            accH[mt][nt][0] = accH[mt][nt][1] = 0u;

    ISSUE_STAGE(0); cp_commit();
    ISSUE_STAGE(1); cp_commit();

    uint32_t lrow  = (uint32_t)(lane & 15);
    uint32_t khalf = (uint32_t)((lane >> 4) * 16);
    uint32_t boff = (uint32_t)(warpN * 64) * B_ROW + lrow * B_ROW + khalf + A_TILE;

    for (int ck = 0; ck < nchunks; ++ck) {
        cp_wait1();               // stage ck landed (this thread's groups)
        __syncthreads();          // landed CTA-wide

        uint32_t stoff = (uint32_t)(ck & 1) * STAGE_BYTES;
        const float2* As2 = reinterpret_cast<const float2*>(smem_buf + stoff);
        uint32_t bAddr = sb + stoff + boff;

        if (ck < nchunks - 2)
            chunk_body<false>(As2, bAddr, accH, 0, warpN, warpM, lane);
        else
            chunk_body<true>(As2, bAddr, accH, 64 * ck - n0, warpN, warpM, lane);

        __syncthreads();          // compute on buffer (ck&1) done CTA-wide
        if (ck + 2 < nchunks) {
            ISSUE_STAGE(ck & 1);
        }
        cp_commit();              // uniform group accounting
    }

    // ---------------- epilogue: rowdot S * x (x fp32 direct) ----------------
    if (tid < 128) part[tid] = 0.0f;
    __syncthreads();

    #pragma unroll
    for (int mt = 0; mt < 2; ++mt) {
        float ps0 = 0.0f, ps1 = 0.0f;
        #pragma unroll
        for (int nt = 0; nt < 8; ++nt) {
            int col  = n0 + warpN * 64 + nt * 8 + (lane & 3) * 2;
            int rowg = m0 + warpM * 32 + mt * 16 + (lane >> 2);
            float2 x0 = *reinterpret_cast<const float2*>(x + (size_t)rowg * F + col);
            float2 x1 = *reinterpret_cast<const float2*>(x + (size_t)(rowg + 8) * F + col);
            float2 s0 = __half22float2(*reinterpret_cast<__half2*>(&accH[mt][nt][0]));
            float2 s1 = __half22float2(*reinterpret_cast<__half2*>(&accH[mt][nt][1]));
            ps0 += s0.x * x0.x + s0.y * x0.y;
            ps1 += s1.x * x1.x + s1.y * x1.y;
        }
        ps0 += __shfl_xor_sync(0xffffffffu, ps0, 1);
        ps0 += __shfl_xor_sync(0xffffffffu, ps0, 2);
        ps1 += __shfl_xor_sync(0xffffffffu, ps1, 1);
        ps1 += __shfl_xor_sync(0xffffffffu, ps1, 2);
        if ((lane & 3) == 0) {
            int rl = warpM * 32 + mt * 16 + (lane >> 2);
            atomicAdd(&part[rl], ps0);
            atomicAdd(&part[rl + 8], ps1);
        }
    }
    __syncthreads();
    if (tid < 128) d_part[by * BATCHN + m0 + tid] = part[tid];
}

// ---------------- launch ----------------
extern "C" void kernel_launch(void* const* d_in, const int* in_sizes, int n_in,
                              void* d_out, int out_size) {
    const float* x = (const float*)d_in[0];
    const float* w = (const float*)d_in[1];
    float* out = (float*)d_out;

    prep_w_kernel<<<(F * F / 2) / 256, 256>>>(w);

    cudaFuncSetAttribute(poly2_gemm_kernel,
                         cudaFuncAttributeMaxDynamicSharedMemorySize, SMEM_TOTAL);
    dim3 grid(BATCHN / M_TILE, NBLK);
    poly2_gemm_kernel<<<grid, NTHREADS, SMEM_TOTAL>>>(x);

    sigmoid_kernel<<<BATCHN / 256, 256>>>(out);
}